// round 2
// baseline (speedup 1.0000x reference)
#include <cuda_runtime.h>

// fm: (1, 256, 256, 256) fp32 NHWC; rois: (2000, 5) int32 [b, x, y, w, h]; pool = 7.
#define FM_W 256
#define FM_C 256
#define POOLSZ 7

__global__ __launch_bounds__(256) void roi_pool_kernel(
    const float* __restrict__ fm,      // [H, W, C]
    const int* __restrict__ rois,      // [N, 5]
    float* __restrict__ out,           // [N, 7, 7, C]
    int n_pix)                         // N * 49
{
    int pid = blockIdx.x * 4 + threadIdx.y;
    if (pid >= n_pix) return;

    int roi = pid / 49;
    int rem = pid - roi * 49;
    int py = rem / 7;
    int px = rem - py * 7;

    int rx = __ldg(&rois[roi * 5 + 1]);
    int ry = __ldg(&rois[roi * 5 + 2]);
    int rw = __ldg(&rois[roi * 5 + 3]);
    int rh = __ldg(&rois[roi * 5 + 4]);

    // y axis: f = (py + 0.5) * (h / 7) - 0.5, clamp [0, h-1]
    float lh = (float)rh;
    float fyc = ((float)py + 0.5f) * (lh / (float)POOLSZ) - 0.5f;
    fyc = fminf(fmaxf(fyc, 0.0f), lh - 1.0f);
    int iy0 = (int)floorf(fyc);
    int iy1 = min(iy0 + 1, rh - 1);
    float fy = fyc - (float)iy0;

    // x axis
    float lw = (float)rw;
    float fxc = ((float)px + 0.5f) * (lw / (float)POOLSZ) - 0.5f;
    fxc = fminf(fmaxf(fxc, 0.0f), lw - 1.0f);
    int ix0 = (int)floorf(fxc);
    int ix1 = min(ix0 + 1, rw - 1);
    float fx = fxc - (float)ix0;

    int y0 = ry + iy0, y1 = ry + iy1;
    int x0 = rx + ix0, x1 = rx + ix1;

    const float4* f4 = (const float4*)fm;
    int c = threadIdx.x;

    const float4 g00 = __ldg(&f4[(y0 * FM_W + x0) * (FM_C / 4) + c]);
    const float4 g01 = __ldg(&f4[(y0 * FM_W + x1) * (FM_C / 4) + c]);
    const float4 g10 = __ldg(&f4[(y1 * FM_W + x0) * (FM_C / 4) + c]);
    const float4 g11 = __ldg(&f4[(y1 * FM_W + x1) * (FM_C / 4) + c]);

    float ofx = 1.0f - fx;
    float ofy = 1.0f - fy;

    float4 r;
    r.x = (g00.x * ofx + g01.x * fx) * ofy + (g10.x * ofx + g11.x * fx) * fy;
    r.y = (g00.y * ofx + g01.y * fx) * ofy + (g10.y * ofx + g11.y * fx) * fy;
    r.z = (g00.z * ofx + g01.z * fx) * ofy + (g10.z * ofx + g11.z * fx) * fy;
    r.w = (g00.w * ofx + g01.w * fx) * ofy + (g10.w * ofx + g11.w * fx) * fy;

    // Streaming store: evict-first so the 100MB output stream doesn't evict
    // the 64MB feature map out of L2 (that eviction caused ~43MB/iter of
    // DRAM re-reads in R1's profile).
    __stcs(&((float4*)out)[pid * (FM_C / 4) + c], r);
}

extern "C" void kernel_launch(void* const* d_in, const int* in_sizes, int n_in,
                              void* d_out, int out_size)
{
    const float* fm  = (const float*)d_in[0];
    const int* rois  = (const int*)d_in[1];
    float* out       = (float*)d_out;

    int n_rois = in_sizes[1] / 5;
    int n_pix  = n_rois * POOLSZ * POOLSZ;

    dim3 block(64, 4, 1);
    dim3 grid((n_pix + 3) / 4, 1, 1);
    roi_pool_kernel<<<grid, block>>>(fm, rois, out, n_pix);
}

// round 3
// speedup vs baseline: 1.1070x; 1.1070x over previous
#include <cuda_runtime.h>

// fm: (1, 256, 256, 256) fp32 NHWC; rois: (2000, 5) int32 [b, x, y, w, h]; pool = 7.
#define FM_W 256
#define FM_C 256
#define POOLSZ 7

__global__ __launch_bounds__(256) void roi_pool_kernel(
    const float* __restrict__ fm,      // [H, W, C]
    const int* __restrict__ rois,      // [N, 5]
    float* __restrict__ out)           // [N, 7, 7, C]
{
    int roi = blockIdx.x;
    int tid = threadIdx.x;

    __shared__ int   sx0[POOLSZ], sx1[POOLSZ], sy0[POOLSZ], sy1[POOLSZ];
    __shared__ float sfx[POOLSZ], sfy[POOLSZ];

    // 14 threads compute the two axes' sample coordinates once per ROI.
    if (tid < 2 * POOLSZ) {
        int  p   = (tid >= POOLSZ) ? tid - POOLSZ : tid;
        bool isx = tid < POOLSZ;
        int start = rois[roi * 5 + (isx ? 1 : 2)];
        int len   = rois[roi * 5 + (isx ? 3 : 4)];
        float lf = (float)len;
        float f = ((float)p + 0.5f) * (lf / (float)POOLSZ) - 0.5f;
        f = fminf(fmaxf(f, 0.0f), lf - 1.0f);
        int i0 = (int)floorf(f);
        int i1 = min(i0 + 1, len - 1);
        float fr = f - (float)i0;
        if (isx) { sx0[p] = start + i0; sx1[p] = start + i1; sfx[p] = fr; }
        else     { sy0[p] = start + i0; sy1[p] = start + i1; sfy[p] = fr; }
    }
    __syncthreads();

    int c  = tid & 63;        // channel float4 index 0..63
    int ty = tid >> 6;        // cell-group 0..3

    const float4* f4 = (const float4*)fm;
    float4* o4 = (float4*)out + (size_t)roi * (POOLSZ * POOLSZ) * (FM_C / 4);

    #pragma unroll 2
    for (int cell = ty; cell < POOLSZ * POOLSZ; cell += 4) {
        int py = cell / POOLSZ;            // becomes mul-shift
        int px = cell - py * POOLSZ;

        int y0 = sy0[py], y1 = sy1[py];
        int x0 = sx0[px], x1 = sx1[px];
        float fy = sfy[py], fx = sfx[px];

        const float4 g00 = __ldg(&f4[(y0 * FM_W + x0) * (FM_C / 4) + c]);
        const float4 g01 = __ldg(&f4[(y0 * FM_W + x1) * (FM_C / 4) + c]);
        const float4 g10 = __ldg(&f4[(y1 * FM_W + x0) * (FM_C / 4) + c]);
        const float4 g11 = __ldg(&f4[(y1 * FM_W + x1) * (FM_C / 4) + c]);

        float ofx = 1.0f - fx;
        float ofy = 1.0f - fy;

        float4 r;
        r.x = (g00.x * ofx + g01.x * fx) * ofy + (g10.x * ofx + g11.x * fx) * fy;
        r.y = (g00.y * ofx + g01.y * fx) * ofy + (g10.y * ofx + g11.y * fx) * fy;
        r.z = (g00.z * ofx + g01.z * fx) * ofy + (g10.z * ofx + g11.z * fx) * fy;
        r.w = (g00.w * ofx + g01.w * fx) * ofy + (g10.w * ofx + g11.w * fx) * fy;

        // Streaming store: keep the 100MB output stream from evicting the
        // 64MB feature map out of L2.
        __stcs(&o4[cell * (FM_C / 4) + c], r);
    }
}

extern "C" void kernel_launch(void* const* d_in, const int* in_sizes, int n_in,
                              void* d_out, int out_size)
{
    const float* fm  = (const float*)d_in[0];
    const int* rois  = (const int*)d_in[1];
    float* out       = (float*)d_out;

    int n_rois = in_sizes[1] / 5;

    roi_pool_kernel<<<n_rois, 256>>>(fm, rois, out);
}